// round 7
// baseline (speedup 1.0000x reference)
#include <cuda_runtime.h>
#include <math.h>

#define B_    4
#define N_    8192
#define D_    64
#define S_    1024
#define K_    32
#define CIN_  134
#define HID_  128
#define COUT_ 256
#define C8_   32
#define P_    131072   // B_*S_*K_
#define CTOT_ 518

// ---------------- scratch (device globals; no allocations allowed) --------
__device__ float g_Y [(size_t)CTOT_ * P_];   // dense concat buffer, channel-major
__device__ float g_Xs[(size_t)COUT_ * P_];   // pre-BN conv output scratch
__device__ float g_Wt[300000];               // transposed weights, per-layer slices
__device__ float g_feat[B_*COUT_*S_];
__device__ float g_q[B_*C8_*S_];
__device__ float g_k[B_*C8_*S_];
__device__ float g_v[B_*COUT_*S_];
__device__ float g_E [(size_t)B_*S_*S_];
__device__ float g_Ec[B_*COUT_*COUT_];
__device__ float g_outp[B_*COUT_*S_];
__device__ float g_outc[B_*COUT_*S_];
__device__ float g_mean[COUT_];
__device__ float g_istd[COUT_];
__device__ double g_part[COUT_*8*2];
__device__ int   g_fps [B_*S_];
__device__ float g_nxyz[B_*S_*3];
__device__ int   g_ball[B_*S_*K_];

// ---------------- FPS (one barrier per iteration) ---------------------------
__global__ void fps_kernel(const float* __restrict__ xyz, float* __restrict__ outxyz)
{
    int b = blockIdx.x;
    const float* X = xyz + (size_t)b * N_ * 3;
    int tid = threadIdx.x;                 // 1024 threads
    int lane = tid & 31, wid = tid >> 5;
    float px[8], py[8], pz[8], dist[8];
#pragma unroll
    for (int i = 0; i < 8; i++){
        int j = tid + i * 1024;
        px[i] = X[j*3+0]; py[i] = X[j*3+1]; pz[i] = X[j*3+2];
        dist[i] = 1e10f;
    }
    __shared__ float s_bv[2][32];
    __shared__ int   s_bi[2][32];
    float cx = X[0], cy = X[1], cz = X[2];
    int   far = 0;
    int   p = 0;

    for (int t = 0; t < S_; t++){
        if (tid == 0){
            g_fps[b*S_ + t] = far;
            g_nxyz[(b*S_+t)*3+0] = cx;
            g_nxyz[(b*S_+t)*3+1] = cy;
            g_nxyz[(b*S_+t)*3+2] = cz;
            outxyz[(b*S_+t)*3+0] = cx;
            outxyz[(b*S_+t)*3+1] = cy;
            outxyz[(b*S_+t)*3+2] = cz;
        }
        float bv = -1.0f; int bi = 0;
#pragma unroll
        for (int i = 0; i < 8; i++){
            float dx = px[i]-cx, dy = py[i]-cy, dz = pz[i]-cz;
            float d = fmaf(dz, dz, fmaf(dy, dy, dx*dx));
            float nd = fminf(dist[i], d);
            dist[i] = nd;
            if (nd > bv){ bv = nd; bi = tid + i*1024; }   // ties keep lowest j
        }
        for (int off = 16; off; off >>= 1){
            float ov = __shfl_down_sync(0xffffffffu, bv, off);
            int   oi = __shfl_down_sync(0xffffffffu, bi, off);
            if (ov > bv || (ov == bv && oi < bi)){ bv = ov; bi = oi; }
        }
        if (lane == 0){ s_bv[p][wid] = bv; s_bi[p][wid] = bi; }
        __syncthreads();
        bv = s_bv[p][lane]; bi = s_bi[p][lane];
#pragma unroll
        for (int off = 16; off; off >>= 1){
            float ov = __shfl_xor_sync(0xffffffffu, bv, off);
            int   oi = __shfl_xor_sync(0xffffffffu, bi, off);
            if (ov > bv || (ov == bv && oi < bi)){ bv = ov; bi = oi; }
        }
        far = bi;
        cx = X[far*3+0]; cy = X[far*3+1]; cz = X[far*3+2];   // broadcast L1 hit
        p ^= 1;
    }
}

// ---------------- ball query (one warp per center) -------------------------
__global__ void ball_kernel(const float* __restrict__ xyz)
{
    int gw   = (blockIdx.x * blockDim.x + threadIdx.x) >> 5;
    int lane = threadIdx.x & 31;
    int b = gw >> 10;
    const float* X = xyz + (size_t)b * N_ * 3;
    float cx = g_nxyz[gw*3+0], cy = g_nxyz[gw*3+1], cz = g_nxyz[gw*3+2];
    float cn2 = __fadd_rn(__fadd_rn(__fmul_rn(cx,cx), __fmul_rn(cy,cy)), __fmul_rn(cz,cz));
    int* out = g_ball + gw * K_;
    int cnt = 0;
    for (int base = 0; base < N_ && cnt < K_; base += 32){
        int j = base + lane;
        float x = X[j*3+0], y = X[j*3+1], z = X[j*3+2];
        float pn2 = __fadd_rn(__fadd_rn(__fmul_rn(x,x), __fmul_rn(y,y)), __fmul_rn(z,z));
        float dt  = fmaf(cz, z, fmaf(cy, y, __fmul_rn(cx, x)));
        float d   = __fsub_rn(__fadd_rn(cn2, pn2), __fmul_rn(2.0f, dt));
        bool inb = !(d > 0.04f);
        unsigned msk = __ballot_sync(0xffffffffu, inb);
        int pos = cnt + __popc(msk & ((1u << lane) - 1u));
        if (inb && pos < K_) out[pos] = j;
        cnt += __popc(msk);
    }
    __syncwarp();
    if (cnt < K_){
        int first = out[0];
        for (int pq = cnt + lane; pq < K_; pq += 32) out[pq] = first;
    }
}

// ---------------- build x0 into g_Y channels [0,134) ------------------------
__global__ void build_x0(const float* __restrict__ xyz, const float* __restrict__ pts)
{
    int bs  = blockIdx.x;
    int b   = bs >> 10;
    int tid = threadIdx.x;                  // 256
    __shared__ int   sj[32];
    __shared__ float sgx[32], sgy[32], sgz[32];
    __shared__ float scp[64];
    __shared__ float scen[3];
    if (tid < 32){
        int j = g_ball[bs*K_ + tid]; sj[tid] = j;
        const float* Xp = xyz + ((size_t)b*N_ + j)*3;
        sgx[tid] = Xp[0]; sgy[tid] = Xp[1]; sgz[tid] = Xp[2];
    } else if (tid < 96){
        scp[tid-32] = pts[((size_t)b*N_ + g_fps[bs])*D_ + (tid-32)];
    } else if (tid < 99){
        scen[tid-96] = g_nxyz[bs*3 + (tid-96)];
    }
    __syncthreads();
    const float* Pb = pts + (size_t)b * N_ * D_;
    size_t pbase = (size_t)bs * K_;
    for (int idx = tid; idx < CIN_ * K_; idx += 256){
        int c = idx >> 5, k = idx & 31;
        int j = sj[k];
        float val;
        if (c < 3){
            float g = (c==0) ? sgx[k] : (c==1) ? sgy[k] : sgz[k];
            float cc = scen[c];
            val = (g - cc) - cc;
        } else if (c < 67){
            val = Pb[(size_t)j*D_ + (c-3)] - scp[c-3];
        } else if (c < 70){
            int c3 = c - 67;
            float g = (c3==0) ? sgx[k] : (c3==1) ? sgy[k] : sgz[k];
            val = g - scen[c3];
        } else {
            val = Pb[(size_t)j*D_ + (c-70)];
        }
        g_Y[(size_t)c*P_ + pbase + k] = val;
    }
}

// ---------------- weight transpose: W[M][K] -> Wt[K][M] ----------------------
__global__ void transposeW(const float* __restrict__ W, float* __restrict__ Wt,
                           int M, int Kk)
{
    int i = blockIdx.x * 256 + threadIdx.x;
    if (i < M * Kk){
        int m = i / Kk, k = i - m * Kk;
        Wt[(long)k * M + m] = W[i];
    }
}

// ------------- double-buffered GEMM: 128x128 tile, 8x8/thread ---------------
// C[m][n] = sum_k At[k*M+m] * B[k*Nn+n] (+bias[m]); M, Nn multiples of 128.
__global__ void __launch_bounds__(256, 2)
gemm128db(const float* __restrict__ At, const float* __restrict__ Bm,
          float* __restrict__ C, const float* __restrict__ bias,
          int M, int Nn, int Kk, long sB, long sC)
{
    Bm += (long)blockIdx.z * sB;
    C  += (long)blockIdx.z * sC;
    __shared__ float As[2][8][128];
    __shared__ float Bs[2][8][128];
    int tid = threadIdx.x;
    int n0 = blockIdx.x * 128, m0 = blockIdx.y * 128;
    int lr = tid >> 5;              // 0..7 (k within tile)
    int lc = (tid & 31) << 2;       // 0..124
    int tx = tid & 15, ty = tid >> 4;

    const float4 z4 = make_float4(0.f,0.f,0.f,0.f);
    {
        float4 av = (lr < Kk) ? *(const float4*)(At + (long)lr*M  + m0 + lc) : z4;
        float4 bv = (lr < Kk) ? *(const float4*)(Bm + (long)lr*Nn + n0 + lc) : z4;
        *(float4*)&As[0][lr][lc] = av;
        *(float4*)&Bs[0][lr][lc] = bv;
    }
    __syncthreads();

    float acc[8][8] = {};
    int buf = 0;
    for (int k0 = 8; k0 < Kk; k0 += 8){
        int kg = k0 + lr;
        float4 av = (kg < Kk) ? *(const float4*)(At + (long)kg*M  + m0 + lc) : z4;
        float4 bv = (kg < Kk) ? *(const float4*)(Bm + (long)kg*Nn + n0 + lc) : z4;
#pragma unroll
        for (int kk = 0; kk < 8; kk++){
            float4 a0 = *(const float4*)&As[buf][kk][ty*4];
            float4 a1 = *(const float4*)&As[buf][kk][ty*4 + 64];
            float4 b0 = *(const float4*)&Bs[buf][kk][tx*4];
            float4 b1 = *(const float4*)&Bs[buf][kk][tx*4 + 64];
            float a_[8] = {a0.x,a0.y,a0.z,a0.w,a1.x,a1.y,a1.z,a1.w};
            float b_[8] = {b0.x,b0.y,b0.z,b0.w,b1.x,b1.y,b1.z,b1.w};
#pragma unroll
            for (int i = 0; i < 8; i++)
#pragma unroll
                for (int j = 0; j < 8; j++)
                    acc[i][j] = fmaf(a_[i], b_[j], acc[i][j]);
        }
        *(float4*)&As[buf^1][lr][lc] = av;
        *(float4*)&Bs[buf^1][lr][lc] = bv;
        __syncthreads();
        buf ^= 1;
    }
#pragma unroll
    for (int kk = 0; kk < 8; kk++){
        float4 a0 = *(const float4*)&As[buf][kk][ty*4];
        float4 a1 = *(const float4*)&As[buf][kk][ty*4 + 64];
        float4 b0 = *(const float4*)&Bs[buf][kk][tx*4];
        float4 b1 = *(const float4*)&Bs[buf][kk][tx*4 + 64];
        float a_[8] = {a0.x,a0.y,a0.z,a0.w,a1.x,a1.y,a1.z,a1.w};
        float b_[8] = {b0.x,b0.y,b0.z,b0.w,b1.x,b1.y,b1.z,b1.w};
#pragma unroll
        for (int i = 0; i < 8; i++)
#pragma unroll
            for (int j = 0; j < 8; j++)
                acc[i][j] = fmaf(a_[i], b_[j], acc[i][j]);
    }

#pragma unroll
    for (int i = 0; i < 8; i++){
        int mm = m0 + ((i < 4) ? ty*4 + i : 64 + ty*4 + (i-4));
        float bsv = bias ? bias[mm] : 0.f;
        float* crow = C + (long)mm*Nn + n0;
        *(float4*)&crow[tx*4]      = make_float4(acc[i][0]+bsv,acc[i][1]+bsv,acc[i][2]+bsv,acc[i][3]+bsv);
        *(float4*)&crow[tx*4 + 64] = make_float4(acc[i][4]+bsv,acc[i][5]+bsv,acc[i][6]+bsv,acc[i][7]+bsv);
    }
}

// ---------------- small GEMMs (64x64 tile) for attention --------------------
__global__ void gemm_nn(const float* __restrict__ A, const float* __restrict__ Bm,
                        float* __restrict__ C, const float* __restrict__ bias,
                        int M, int Nn, int Kk, long sA, long sB, long sC)
{
    A  += (long)blockIdx.z * sA;
    Bm += (long)blockIdx.z * sB;
    C  += (long)blockIdx.z * sC;
    __shared__ float As[16][68];
    __shared__ float Bs[16][64];
    int tid = threadIdx.x;
    int m0 = blockIdx.y * 64, n0 = blockIdx.x * 64;
    int ty = tid >> 4, tx = tid & 15;
    float acc[4][4] = {};
    for (int k0 = 0; k0 < Kk; k0 += 16){
#pragma unroll
        for (int i = tid; i < 1024; i += 256){
            int rr = i >> 4, cc = i & 15;
            int mm = m0 + rr, kk = k0 + cc;
            As[cc][rr] = (mm < M && kk < Kk) ? A[(long)mm*Kk + kk] : 0.f;
        }
#pragma unroll
        for (int i = tid; i < 1024; i += 256){
            int rr = i >> 6, cc = i & 63;
            int kk = k0 + rr;
            Bs[rr][cc] = (kk < Kk) ? Bm[(long)kk*Nn + n0 + cc] : 0.f;
        }
        __syncthreads();
#pragma unroll
        for (int kk = 0; kk < 16; kk++){
            float4 a  = *(const float4*)&As[kk][ty*4];
            float4 bv = *(const float4*)&Bs[kk][tx*4];
            float av[4] = {a.x, a.y, a.z, a.w};
            float bb[4] = {bv.x, bv.y, bv.z, bv.w};
#pragma unroll
            for (int i = 0; i < 4; i++)
#pragma unroll
                for (int j = 0; j < 4; j++)
                    acc[i][j] = fmaf(av[i], bb[j], acc[i][j]);
        }
        __syncthreads();
    }
#pragma unroll
    for (int i = 0; i < 4; i++){
        int mm = m0 + ty*4 + i;
        if (mm < M){
            float bsv = bias ? bias[mm] : 0.f;
            float4 o = make_float4(acc[i][0]+bsv, acc[i][1]+bsv, acc[i][2]+bsv, acc[i][3]+bsv);
            *(float4*)&C[(long)mm*Nn + n0 + tx*4] = o;
        }
    }
}

__global__ void gemm_tn(const float* __restrict__ A, const float* __restrict__ Bm,
                        float* __restrict__ C,
                        int M, int Nn, int Kk, int lda, int ldb,
                        long sA, long sB, long sC)
{
    A += (long)blockIdx.z*sA; Bm += (long)blockIdx.z*sB; C += (long)blockIdx.z*sC;
    __shared__ float As[16][64], Bs[16][64];
    int tid = threadIdx.x;
    int m0 = blockIdx.y * 64, n0 = blockIdx.x * 64;
    int ty = tid >> 4, tx = tid & 15;
    float acc[4][4] = {};
    for (int k0 = 0; k0 < Kk; k0 += 16){
#pragma unroll
        for (int i = tid; i < 1024; i += 256){
            int rr = i >> 6, cc = i & 63;
            int kk = k0 + rr;
            As[rr][cc] = (kk < Kk) ? A[(long)kk*lda + m0 + cc] : 0.f;
            Bs[rr][cc] = (kk < Kk) ? Bm[(long)kk*ldb + n0 + cc] : 0.f;
        }
        __syncthreads();
#pragma unroll
        for (int kk = 0; kk < 16; kk++){
            float4 a  = *(const float4*)&As[kk][ty*4];
            float4 bv = *(const float4*)&Bs[kk][tx*4];
            float av[4] = {a.x, a.y, a.z, a.w};
            float bb[4] = {bv.x, bv.y, bv.z, bv.w};
#pragma unroll
            for (int i = 0; i < 4; i++)
#pragma unroll
                for (int j = 0; j < 4; j++)
                    acc[i][j] = fmaf(av[i], bb[j], acc[i][j]);
        }
        __syncthreads();
    }
#pragma unroll
    for (int i = 0; i < 4; i++){
        int mm = m0 + ty*4 + i;
        float4 o = make_float4(acc[i][0], acc[i][1], acc[i][2], acc[i][3]);
        *(float4*)&C[(long)mm*Nn + n0 + tx*4] = o;
    }
}

__global__ void gemm_nt(const float* __restrict__ A, const float* __restrict__ Bm,
                        float* __restrict__ C,
                        int M, int Nn, int Kk, int lda, int ldb,
                        long sA, long sB, long sC)
{
    A += (long)blockIdx.z*sA; Bm += (long)blockIdx.z*sB; C += (long)blockIdx.z*sC;
    __shared__ float As[16][68], Bs[16][68];
    int tid = threadIdx.x;
    int m0 = blockIdx.y * 64, n0 = blockIdx.x * 64;
    int ty = tid >> 4, tx = tid & 15;
    float acc[4][4] = {};
    for (int k0 = 0; k0 < Kk; k0 += 16){
#pragma unroll
        for (int i = tid; i < 1024; i += 256){
            int mm = i >> 4, kd = i & 15;
            int kk = k0 + kd;
            As[kd][mm] = (kk < Kk) ? A[(long)(m0+mm)*lda + kk] : 0.f;
            Bs[kd][mm] = (kk < Kk) ? Bm[(long)(n0+mm)*ldb + kk] : 0.f;
        }
        __syncthreads();
#pragma unroll
        for (int kk = 0; kk < 16; kk++){
            float4 a  = *(const float4*)&As[kk][ty*4];
            float4 bv = *(const float4*)&Bs[kk][tx*4];
            float av[4] = {a.x, a.y, a.z, a.w};
            float bb[4] = {bv.x, bv.y, bv.z, bv.w};
#pragma unroll
            for (int i = 0; i < 4; i++)
#pragma unroll
                for (int j = 0; j < 4; j++)
                    acc[i][j] = fmaf(av[i], bb[j], acc[i][j]);
        }
        __syncthreads();
    }
#pragma unroll
    for (int i = 0; i < 4; i++){
        int mm = m0 + ty*4 + i;
        float4 o = make_float4(acc[i][0], acc[i][1], acc[i][2], acc[i][3]);
        *(float4*)&C[(long)mm*Nn + n0 + tx*4] = o;
    }
}

// ---- Kahan-compensated fp32 GEMMs for the channel-attention path ----------
__global__ void gemm_nt_kah(const float* __restrict__ A, const float* __restrict__ Bm,
                            float* __restrict__ C,
                            int M, int Nn, int Kk, int lda, int ldb,
                            long sA, long sB, long sC)
{
    A += (long)blockIdx.z*sA; Bm += (long)blockIdx.z*sB; C += (long)blockIdx.z*sC;
    __shared__ float As[16][68], Bs[16][68];
    int tid = threadIdx.x;
    int m0 = blockIdx.y * 64, n0 = blockIdx.x * 64;
    int ty = tid >> 4, tx = tid & 15;
    float acc[4][4] = {};
    float cmp[4][4] = {};
    for (int k0 = 0; k0 < Kk; k0 += 16){
#pragma unroll
        for (int i = tid; i < 1024; i += 256){
            int mm = i >> 4, kd = i & 15;
            int kk = k0 + kd;
            As[kd][mm] = (kk < Kk) ? A[(long)(m0+mm)*lda + kk] : 0.f;
            Bs[kd][mm] = (kk < Kk) ? Bm[(long)(n0+mm)*ldb + kk] : 0.f;
        }
        __syncthreads();
#pragma unroll
        for (int kk = 0; kk < 16; kk++){
            float4 a  = *(const float4*)&As[kk][ty*4];
            float4 bv = *(const float4*)&Bs[kk][tx*4];
            float av[4] = {a.x, a.y, a.z, a.w};
            float bb[4] = {bv.x, bv.y, bv.z, bv.w};
#pragma unroll
            for (int i = 0; i < 4; i++)
#pragma unroll
                for (int j = 0; j < 4; j++){
                    float y = fmaf(av[i], bb[j], -cmp[i][j]);
                    float t = acc[i][j] + y;
                    cmp[i][j] = (t - acc[i][j]) - y;
                    acc[i][j] = t;
                }
        }
        __syncthreads();
    }
#pragma unroll
    for (int i = 0; i < 4; i++){
        int mm = m0 + ty*4 + i;
        float4 o = make_float4(acc[i][0], acc[i][1], acc[i][2], acc[i][3]);
        *(float4*)&C[(long)mm*Nn + n0 + tx*4] = o;
    }
}

__global__ void gemm_nn_kah(const float* __restrict__ A, const float* __restrict__ Bm,
                            float* __restrict__ C,
                            int M, int Nn, int Kk, long sA, long sB, long sC)
{
    A  += (long)blockIdx.z * sA;
    Bm += (long)blockIdx.z * sB;
    C  += (long)blockIdx.z * sC;
    __shared__ float As[16][68];
    __shared__ float Bs[16][64];
    int tid = threadIdx.x;
    int m0 = blockIdx.y * 64, n0 = blockIdx.x * 64;
    int ty = tid >> 4, tx = tid & 15;
    float acc[4][4] = {};
    float cmp[4][4] = {};
    for (int k0 = 0; k0 < Kk; k0 += 16){
#pragma unroll
        for (int i = tid; i < 1024; i += 256){
            int rr = i >> 4, cc = i & 15;
            int mm = m0 + rr, kk = k0 + cc;
            As[cc][rr] = (mm < M && kk < Kk) ? A[(long)mm*Kk + kk] : 0.f;
        }
#pragma unroll
        for (int i = tid; i < 1024; i += 256){
            int rr = i >> 6, cc = i & 63;
            int kk = k0 + rr;
            Bs[rr][cc] = (kk < Kk) ? Bm[(long)kk*Nn + n0 + cc] : 0.f;
        }
        __syncthreads();
#pragma unroll
        for (int kk = 0; kk < 16; kk++){
            float4 a  = *(const float4*)&As[kk][ty*4];
            float4 bv = *(const float4*)&Bs[kk][tx*4];
            float av[4] = {a.x, a.y, a.z, a.w};
            float bb[4] = {bv.x, bv.y, bv.z, bv.w};
#pragma unroll
            for (int i = 0; i < 4; i++)
#pragma unroll
                for (int j = 0; j < 4; j++){
                    float y = fmaf(av[i], bb[j], -cmp[i][j]);
                    float t = acc[i][j] + y;
                    cmp[i][j] = (t - acc[i][j]) - y;
                    acc[i][j] = t;
                }
        }
        __syncthreads();
    }
#pragma unroll
    for (int i = 0; i < 4; i++){
        int mm = m0 + ty*4 + i;
        float4 o = make_float4(acc[i][0], acc[i][1], acc[i][2], acc[i][3]);
        *(float4*)&C[(long)mm*Nn + n0 + tx*4] = o;
    }
}

// ---------------- BatchNorm (training mode) ---------------------------------
__global__ void bn_stats_part(const float* __restrict__ Xs)
{
    int c = blockIdx.x, blk = blockIdx.y;
    const float4* xp = (const float4*)(Xs + (size_t)c * P_ + (size_t)blk * (P_/8));
    int tid = threadIdx.x;
    double s = 0.0, ss = 0.0;
    const int nvec = (P_/8)/4;
    for (int p = tid; p < nvec; p += 256){
        float4 v = xp[p];
        s  += (double)v.x + (double)v.y + (double)v.z + (double)v.w;
        ss += (double)v.x*v.x + (double)v.y*v.y + (double)v.z*v.z + (double)v.w*v.w;
    }
    __shared__ double sh0[256], sh1[256];
    sh0[tid] = s; sh1[tid] = ss; __syncthreads();
    for (int off = 128; off; off >>= 1){
        if (tid < off){ sh0[tid] += sh0[tid+off]; sh1[tid] += sh1[tid+off]; }
        __syncthreads();
    }
    if (tid == 0){
        g_part[(c*8 + blk)*2 + 0] = sh0[0];
        g_part[(c*8 + blk)*2 + 1] = sh1[0];
    }
}

__global__ void bn_stats_final(int C)
{
    int c = threadIdx.x;
    if (c < C){
        double s = 0.0, ss = 0.0;
#pragma unroll
        for (int j = 0; j < 8; j++){
            s  += g_part[(c*8+j)*2+0];
            ss += g_part[(c*8+j)*2+1];
        }
        double m   = s / (double)P_;
        double var = ss / (double)P_ - m*m;
        g_mean[c] = (float)m;
        g_istd[c] = (float)(1.0 / sqrt(var + 1e-5));
    }
}

__global__ void bn_apply_relu(const float* __restrict__ Xs, float* __restrict__ dst,
                              const float* __restrict__ gg, const float* __restrict__ be)
{
    size_t i = (size_t)blockIdx.x * 256 + threadIdx.x;    // float4 index
    int c = (int)(i >> 15);
    float m = g_mean[c], is = g_istd[c], gv = gg[c], bb = be[c];
    float4 v = ((const float4*)Xs)[i];
    float4 o;
    o.x = fmaxf((v.x - m)*is*gv + bb, 0.f);
    o.y = fmaxf((v.y - m)*is*gv + bb, 0.f);
    o.z = fmaxf((v.z - m)*is*gv + bb, 0.f);
    o.w = fmaxf((v.w - m)*is*gv + bb, 0.f);
    ((float4*)dst)[i] = o;
}

// ------- fused layer-4 BN + ReLU + max over K --------------------------------
__global__ void bn_relu_maxk(const float* __restrict__ Xs,
                             const float* __restrict__ gg, const float* __restrict__ be)
{
    int i = blockIdx.x * 256 + threadIdx.x;           // over B*COUT*S = 2^20
    int s = i & 1023, c = (i >> 10) & 255, b = i >> 18;
    float m = g_mean[c], is = g_istd[c], gv = gg[c], bb = be[c];
    float sc = is * gv;
    const float4* src = (const float4*)(Xs + (size_t)c * P_ + ((size_t)(b*S_ + s)) * K_);
    float best = 0.f;
#pragma unroll
    for (int k = 0; k < 8; k++){
        float4 v = src[k];
        best = fmaxf(best, (v.x - m)*sc + bb);
        best = fmaxf(best, (v.y - m)*sc + bb);
        best = fmaxf(best, (v.z - m)*sc + bb);
        best = fmaxf(best, (v.w - m)*sc + bb);
    }
    g_feat[i] = best;
}

// ---------------- softmaxes ---------------------------------------------------
__global__ void softmax_rows_1024(float* __restrict__ E)
{
    int row = blockIdx.x;
    float* e = E + (size_t)row * 1024;
    int tid = threadIdx.x;
    __shared__ float sh[256];
    float mx = -3.402823466e38f;
    for (int c = tid; c < 1024; c += 256) mx = fmaxf(mx, e[c]);
    sh[tid] = mx; __syncthreads();
    for (int off = 128; off; off >>= 1){ if (tid < off) sh[tid] = fmaxf(sh[tid], sh[tid+off]); __syncthreads(); }
    mx = sh[0]; __syncthreads();
    float sum = 0.f;
    float vals[4];
#pragma unroll
    for (int q = 0; q < 4; q++){
        int c = tid + q*256;
        float v = expf(e[c] - mx);
        vals[q] = v; sum += v;
    }
    sh[tid] = sum; __syncthreads();
    for (int off = 128; off; off >>= 1){ if (tid < off) sh[tid] += sh[tid+off]; __syncthreads(); }
    float inv = 1.0f / sh[0];
#pragma unroll
    for (int q = 0; q < 4; q++) e[tid + q*256] = vals[q] * inv;
}

__global__ void softmax_c_kernel(float* __restrict__ E)
{
    int row = blockIdx.x;                   // B*COUT rows of 256
    float* e = E + (size_t)row * 256;
    int tid = threadIdx.x;
    __shared__ double sh[256];
    double v = (double)e[tid];
    sh[tid] = v; __syncthreads();
    for (int off = 128; off; off >>= 1){ if (tid < off) sh[tid] = fmax(sh[tid], sh[tid+off]); __syncthreads(); }
    double m1 = sh[0]; __syncthreads();
    double t = m1 - v;
    sh[tid] = t; __syncthreads();
    for (int off = 128; off; off >>= 1){ if (tid < off) sh[tid] = fmax(sh[tid], sh[tid+off]); __syncthreads(); }
    double mt = sh[0]; __syncthreads();
    double ex = exp(t - mt);
    sh[tid] = ex; __syncthreads();
    for (int off = 128; off; off >>= 1){ if (tid < off) sh[tid] += sh[tid+off]; __syncthreads(); }
    e[tid] = (float)(ex / sh[0]);
}

// ---------------- finalize -----------------------------------------------------
__global__ void finalize_kernel(float* __restrict__ out, const float* __restrict__ gamma)
{
    int i = blockIdx.x * 256 + threadIdx.x;   // output-major (b,s,c), 2^20 total
    int c = i & 255, s = (i >> 8) & 1023, b = i >> 18;
    size_t f = ((size_t)(b*COUT_ + c)) * S_ + s;
    float g = gamma[0];
    float val = g * (g_outp[f] + g_outc[f]) + 2.0f * g_feat[f];
    out[(size_t)B_*S_*3 + i] = val;
}

// ---------------- launch -------------------------------------------------------
extern "C" void kernel_launch(void* const* d_in, const int* in_sizes, int n_in,
                              void* d_out, int out_size)
{
    const float* xyz    = (const float*)d_in[0];
    const float* points = (const float*)d_in[1];
    const float* W[4]  = {(const float*)d_in[2],  (const float*)d_in[6],
                          (const float*)d_in[10], (const float*)d_in[14]};
    const float* gl[4] = {(const float*)d_in[4],  (const float*)d_in[8],
                          (const float*)d_in[12], (const float*)d_in[16]};
    const float* bel[4]= {(const float*)d_in[5],  (const float*)d_in[9],
                          (const float*)d_in[13], (const float*)d_in[17]};
    const float* Wq = (const float*)d_in[18]; const float* bq = (const float*)d_in[19];
    const float* Wk = (const float*)d_in[20]; const float* bk = (const float*)d_in[21];
    const float* Wv = (const float*)d_in[22]; const float* bv = (const float*)d_in[23];
    const float* gamma = (const float*)d_in[24];
    float* out = (float*)d_out;

    float *Y, *Xs, *Wt, *feat, *q, *k, *v, *E, *Ec, *outp, *outc;
    cudaGetSymbolAddress((void**)&Y,    g_Y);
    cudaGetSymbolAddress((void**)&Xs,   g_Xs);
    cudaGetSymbolAddress((void**)&Wt,   g_Wt);
    cudaGetSymbolAddress((void**)&feat, g_feat);
    cudaGetSymbolAddress((void**)&q,    g_q);
    cudaGetSymbolAddress((void**)&k,    g_k);
    cudaGetSymbolAddress((void**)&v,    g_v);
    cudaGetSymbolAddress((void**)&E,    g_E);
    cudaGetSymbolAddress((void**)&Ec,   g_Ec);
    cudaGetSymbolAddress((void**)&outp, g_outp);
    cudaGetSymbolAddress((void**)&outc, g_outc);

    int   Kl[4]  = {CIN_, CIN_+HID_, CIN_+2*HID_, CIN_+3*HID_};
    int   COl[4] = {HID_, HID_, HID_, COUT_};
    // per-layer Wt slice offsets (+ Wv at the end)
    long Woff[5];
    {
        long o = 0;
        for (int l = 0; l < 4; l++){ Woff[l] = o; o += (long)Kl[l]*COl[l]; }
        Woff[4] = o;
    }

    // hoisted weight transposes (independent of geometry pipeline)
    for (int l = 0; l < 4; l++){
        int Melem = COl[l]*Kl[l];
        transposeW<<<(Melem + 255)/256, 256>>>(W[l], Wt + Woff[l], COl[l], Kl[l]);
    }
    transposeW<<<(COUT_*COUT_ + 255)/256, 256>>>(Wv, Wt + Woff[4], COUT_, COUT_);

    // stage 1-2: FPS, ball query, gather/build x0
    fps_kernel<<<B_, 1024>>>(xyz, out);
    ball_kernel<<<(B_*S_*32)/256, 256>>>(xyz);
    build_x0<<<B_*S_, 256>>>(xyz, points);

    // stage 3: DenseNet (conv -> BN stats -> BN+relu / fused maxk)
    float* dst[4] = {Y + (size_t)CIN_*P_, Y + (size_t)(CIN_+HID_)*P_,
                     Y + (size_t)(CIN_+2*HID_)*P_, nullptr};
    for (int l = 0; l < 4; l++){
        gemm128db<<<dim3(P_/128, COl[l]/128, 1), 256>>>(Wt + Woff[l], Y, Xs, nullptr,
                                                        COl[l], P_, Kl[l], 0, 0);
        bn_stats_part<<<dim3(COl[l], 8), 256>>>(Xs);
        bn_stats_final<<<1, 256>>>(COl[l]);
        if (l < 3)
            bn_apply_relu<<<(COl[l]*(P_/1024)), 256>>>(Xs, dst[l], gl[l], bel[l]);
        else
            bn_relu_maxk<<<(B_*COUT_*S_)/256, 256>>>(Xs, gl[l], bel[l]);
    }

    // stage 5: dual attention
    long fS = (long)COUT_ * S_;
    gemm_nn<<<dim3(S_/64, 1, B_), 256>>>(Wq, feat, q, bq, C8_,  S_, COUT_, 0, fS, (long)C8_*S_);
    gemm_nn<<<dim3(S_/64, 1, B_), 256>>>(Wk, feat, k, bk, C8_,  S_, COUT_, 0, fS, (long)C8_*S_);
    gemm128db<<<dim3(S_/128, COUT_/128, B_), 256>>>(Wt + Woff[4], feat, v, bv,
                                                    COUT_, S_, COUT_, fS, fS);

    gemm_tn<<<dim3(S_/64, S_/64, B_), 256>>>(q, k, E, S_, S_, C8_, S_, S_,
                                             (long)C8_*S_, (long)C8_*S_, (long)S_*S_);
    softmax_rows_1024<<<B_*S_, 256>>>(E);
    gemm_nt<<<dim3(S_/64, COUT_/64, B_), 256>>>(v, E, outp, COUT_, S_, S_, S_, S_,
                                                fS, (long)S_*S_, fS);

    // channel attention — Kahan-compensated fp32 energy + out_c, f64 softmax
    gemm_nt_kah<<<dim3(COUT_/64, COUT_/64, B_), 256>>>(
        feat, feat, Ec, COUT_, COUT_, S_, S_, S_, fS, fS, (long)COUT_*COUT_);
    softmax_c_kernel<<<B_*COUT_, 256>>>(Ec);
    gemm_nn_kah<<<dim3(S_/64, COUT_/64, B_), 256>>>(
        Ec, feat, outc, COUT_, S_, COUT_, (long)COUT_*COUT_, fS, fS);

    finalize_kernel<<<(B_*S_*COUT_)/256, 256>>>(out, gamma);
}

// round 8
// speedup vs baseline: 1.0478x; 1.0478x over previous
#include <cuda_runtime.h>
#include <math.h>

#define B_    4
#define N_    8192
#define D_    64
#define S_    1024
#define K_    32
#define CIN_  134
#define HID_  128
#define COUT_ 256
#define C8_   32
#define P_    131072   // B_*S_*K_
#define CTOT_ 518
#define NEG_INF_ (-3.402823466e38f)

// ---------------- scratch (device globals; no allocations allowed) --------
__device__ float g_Y [(size_t)CTOT_ * P_];   // dense concat buffer (RAW conv outputs), channel-major
__device__ float g_Xs[(size_t)COUT_ * P_];   // layer-4 raw conv output
__device__ float g_Wt[300000];               // transposed weights, per-layer slices
__device__ float4 g_prm[CTOT_];              // per-channel (mean, istd*gamma, beta, floor)
__device__ float g_feat[B_*COUT_*S_];
__device__ float g_q[B_*C8_*S_];
__device__ float g_k[B_*C8_*S_];
__device__ float g_v[B_*COUT_*S_];
__device__ float g_E [(size_t)B_*S_*S_];
__device__ float g_Ec[B_*COUT_*COUT_];
__device__ float g_outp[B_*COUT_*S_];
__device__ float g_outc[B_*COUT_*S_];
__device__ float g_mean[COUT_];
__device__ float g_istd[COUT_];
__device__ double g_part[COUT_*8*2];
__device__ int   g_fps [B_*S_];
__device__ float g_nxyz[B_*S_*3];
__device__ int   g_ball[B_*S_*K_];

// ---------------- FPS (one barrier per iteration) ---------------------------
__global__ void fps_kernel(const float* __restrict__ xyz, float* __restrict__ outxyz)
{
    int b = blockIdx.x;
    const float* X = xyz + (size_t)b * N_ * 3;
    int tid = threadIdx.x;                 // 1024 threads
    int lane = tid & 31, wid = tid >> 5;
    float px[8], py[8], pz[8], dist[8];
#pragma unroll
    for (int i = 0; i < 8; i++){
        int j = tid + i * 1024;
        px[i] = X[j*3+0]; py[i] = X[j*3+1]; pz[i] = X[j*3+2];
        dist[i] = 1e10f;
    }
    __shared__ float s_bv[2][32];
    __shared__ int   s_bi[2][32];
    float cx = X[0], cy = X[1], cz = X[2];
    int   far = 0;
    int   p = 0;

    for (int t = 0; t < S_; t++){
        if (tid == 0){
            g_fps[b*S_ + t] = far;
            g_nxyz[(b*S_+t)*3+0] = cx;
            g_nxyz[(b*S_+t)*3+1] = cy;
            g_nxyz[(b*S_+t)*3+2] = cz;
            outxyz[(b*S_+t)*3+0] = cx;
            outxyz[(b*S_+t)*3+1] = cy;
            outxyz[(b*S_+t)*3+2] = cz;
        }
        float bv = -1.0f; int bi = 0;
#pragma unroll
        for (int i = 0; i < 8; i++){
            float dx = px[i]-cx, dy = py[i]-cy, dz = pz[i]-cz;
            float d = fmaf(dz, dz, fmaf(dy, dy, dx*dx));
            float nd = fminf(dist[i], d);
            dist[i] = nd;
            if (nd > bv){ bv = nd; bi = tid + i*1024; }   // ties keep lowest j
        }
        for (int off = 16; off; off >>= 1){
            float ov = __shfl_down_sync(0xffffffffu, bv, off);
            int   oi = __shfl_down_sync(0xffffffffu, bi, off);
            if (ov > bv || (ov == bv && oi < bi)){ bv = ov; bi = oi; }
        }
        if (lane == 0){ s_bv[p][wid] = bv; s_bi[p][wid] = bi; }
        __syncthreads();
        bv = s_bv[p][lane]; bi = s_bi[p][lane];
#pragma unroll
        for (int off = 16; off; off >>= 1){
            float ov = __shfl_xor_sync(0xffffffffu, bv, off);
            int   oi = __shfl_xor_sync(0xffffffffu, bi, off);
            if (ov > bv || (ov == bv && oi < bi)){ bv = ov; bi = oi; }
        }
        far = bi;
        cx = X[far*3+0]; cy = X[far*3+1]; cz = X[far*3+2];   // broadcast L1 hit
        p ^= 1;
    }
}

// ---------------- ball query (one warp per center) -------------------------
__global__ void ball_kernel(const float* __restrict__ xyz)
{
    int gw   = (blockIdx.x * blockDim.x + threadIdx.x) >> 5;
    int lane = threadIdx.x & 31;
    int b = gw >> 10;
    const float* X = xyz + (size_t)b * N_ * 3;
    float cx = g_nxyz[gw*3+0], cy = g_nxyz[gw*3+1], cz = g_nxyz[gw*3+2];
    float cn2 = __fadd_rn(__fadd_rn(__fmul_rn(cx,cx), __fmul_rn(cy,cy)), __fmul_rn(cz,cz));
    int* out = g_ball + gw * K_;
    int cnt = 0;
    for (int base = 0; base < N_ && cnt < K_; base += 32){
        int j = base + lane;
        float x = X[j*3+0], y = X[j*3+1], z = X[j*3+2];
        float pn2 = __fadd_rn(__fadd_rn(__fmul_rn(x,x), __fmul_rn(y,y)), __fmul_rn(z,z));
        float dt  = fmaf(cz, z, fmaf(cy, y, __fmul_rn(cx, x)));
        float d   = __fsub_rn(__fadd_rn(cn2, pn2), __fmul_rn(2.0f, dt));
        bool inb = !(d > 0.04f);
        unsigned msk = __ballot_sync(0xffffffffu, inb);
        int pos = cnt + __popc(msk & ((1u << lane) - 1u));
        if (inb && pos < K_) out[pos] = j;
        cnt += __popc(msk);
    }
    __syncwarp();
    if (cnt < K_){
        int first = out[0];
        for (int pq = cnt + lane; pq < K_; pq += 32) out[pq] = first;
    }
}

// ---------------- build x0 into g_Y channels [0,134) ------------------------
__global__ void build_x0(const float* __restrict__ xyz, const float* __restrict__ pts)
{
    int bs  = blockIdx.x;
    int b   = bs >> 10;
    int tid = threadIdx.x;                  // 256
    __shared__ int   sj[32];
    __shared__ float sgx[32], sgy[32], sgz[32];
    __shared__ float scp[64];
    __shared__ float scen[3];
    if (tid < 32){
        int j = g_ball[bs*K_ + tid]; sj[tid] = j;
        const float* Xp = xyz + ((size_t)b*N_ + j)*3;
        sgx[tid] = Xp[0]; sgy[tid] = Xp[1]; sgz[tid] = Xp[2];
    } else if (tid < 96){
        scp[tid-32] = pts[((size_t)b*N_ + g_fps[bs])*D_ + (tid-32)];
    } else if (tid < 99){
        scen[tid-96] = g_nxyz[bs*3 + (tid-96)];
    }
    __syncthreads();
    const float* Pb = pts + (size_t)b * N_ * D_;
    size_t pbase = (size_t)bs * K_;
    for (int idx = tid; idx < CIN_ * K_; idx += 256){
        int c = idx >> 5, k = idx & 31;
        int j = sj[k];
        float val;
        if (c < 3){
            float g = (c==0) ? sgx[k] : (c==1) ? sgy[k] : sgz[k];
            float cc = scen[c];
            val = (g - cc) - cc;
        } else if (c < 67){
            val = Pb[(size_t)j*D_ + (c-3)] - scp[c-3];
        } else if (c < 70){
            int c3 = c - 67;
            float g = (c3==0) ? sgx[k] : (c3==1) ? sgy[k] : sgz[k];
            val = g - scen[c3];
        } else {
            val = Pb[(size_t)j*D_ + (c-70)];
        }
        g_Y[(size_t)c*P_ + pbase + k] = val;
    }
}

// ---------------- init per-channel BN params to identity --------------------
__global__ void init_prm()
{
    int i = blockIdx.x * 256 + threadIdx.x;
    if (i < CTOT_) g_prm[i] = make_float4(0.f, 1.f, 0.f, NEG_INF_);
}

// ---------------- weight transpose: W[M][K] -> Wt[K][M] ----------------------
__global__ void transposeW(const float* __restrict__ W, float* __restrict__ Wt,
                           int M, int Kk)
{
    int i = blockIdx.x * 256 + threadIdx.x;
    if (i < M * Kk){
        int m = i / Kk, k = i - m * Kk;
        Wt[(long)k * M + m] = W[i];
    }
}

// ------------- double-buffered GEMM: 128x128 tile, 8x8/thread ---------------
// C[m][n] = sum_k f(At[k*M+m]? no: f applies to B) ; B rows are channels:
// bval = max((raw - prm.x)*prm.y + prm.z, prm.w) when prm != nullptr.
__global__ void __launch_bounds__(256, 2)
gemm128db(const float* __restrict__ At, const float* __restrict__ Bm,
          float* __restrict__ C, const float* __restrict__ bias,
          const float4* __restrict__ prm,
          int M, int Nn, int Kk, long sB, long sC)
{
    Bm += (long)blockIdx.z * sB;
    C  += (long)blockIdx.z * sC;
    __shared__ float As[2][8][128];
    __shared__ float Bs[2][8][128];
    int tid = threadIdx.x;
    int n0 = blockIdx.x * 128, m0 = blockIdx.y * 128;
    int lr = tid >> 5;              // 0..7 (k within tile)
    int lc = (tid & 31) << 2;       // 0..124
    int tx = tid & 15, ty = tid >> 4;

    const float4 z4 = make_float4(0.f,0.f,0.f,0.f);
    {
        float4 av = (lr < Kk) ? *(const float4*)(At + (long)lr*M  + m0 + lc) : z4;
        float4 bv = z4;
        if (lr < Kk){
            bv = *(const float4*)(Bm + (long)lr*Nn + n0 + lc);
            if (prm){
                float4 pp = prm[lr];
                bv.x = fmaxf((bv.x - pp.x)*pp.y + pp.z, pp.w);
                bv.y = fmaxf((bv.y - pp.x)*pp.y + pp.z, pp.w);
                bv.z = fmaxf((bv.z - pp.x)*pp.y + pp.z, pp.w);
                bv.w = fmaxf((bv.w - pp.x)*pp.y + pp.z, pp.w);
            }
        }
        *(float4*)&As[0][lr][lc] = av;
        *(float4*)&Bs[0][lr][lc] = bv;
    }
    __syncthreads();

    float acc[8][8] = {};
    int buf = 0;
    for (int k0 = 8; k0 < Kk; k0 += 8){
        int kg = k0 + lr;
        float4 av = z4, bv = z4;
        if (kg < Kk){
            av = *(const float4*)(At + (long)kg*M  + m0 + lc);
            bv = *(const float4*)(Bm + (long)kg*Nn + n0 + lc);
            if (prm){
                float4 pp = prm[kg];
                bv.x = fmaxf((bv.x - pp.x)*pp.y + pp.z, pp.w);
                bv.y = fmaxf((bv.y - pp.x)*pp.y + pp.z, pp.w);
                bv.z = fmaxf((bv.z - pp.x)*pp.y + pp.z, pp.w);
                bv.w = fmaxf((bv.w - pp.x)*pp.y + pp.z, pp.w);
            }
        }
#pragma unroll
        for (int kk = 0; kk < 8; kk++){
            float4 a0 = *(const float4*)&As[buf][kk][ty*4];
            float4 a1 = *(const float4*)&As[buf][kk][ty*4 + 64];
            float4 b0 = *(const float4*)&Bs[buf][kk][tx*4];
            float4 b1 = *(const float4*)&Bs[buf][kk][tx*4 + 64];
            float a_[8] = {a0.x,a0.y,a0.z,a0.w,a1.x,a1.y,a1.z,a1.w};
            float b_[8] = {b0.x,b0.y,b0.z,b0.w,b1.x,b1.y,b1.z,b1.w};
#pragma unroll
            for (int i = 0; i < 8; i++)
#pragma unroll
                for (int j = 0; j < 8; j++)
                    acc[i][j] = fmaf(a_[i], b_[j], acc[i][j]);
        }
        *(float4*)&As[buf^1][lr][lc] = av;
        *(float4*)&Bs[buf^1][lr][lc] = bv;
        __syncthreads();
        buf ^= 1;
    }
#pragma unroll
    for (int kk = 0; kk < 8; kk++){
        float4 a0 = *(const float4*)&As[buf][kk][ty*4];
        float4 a1 = *(const float4*)&As[buf][kk][ty*4 + 64];
        float4 b0 = *(const float4*)&Bs[buf][kk][tx*4];
        float4 b1 = *(const float4*)&Bs[buf][kk][tx*4 + 64];
        float a_[8] = {a0.x,a0.y,a0.z,a0.w,a1.x,a1.y,a1.z,a1.w};
        float b_[8] = {b0.x,b0.y,b0.z,b0.w,b1.x,b1.y,b1.z,b1.w};
#pragma unroll
        for (int i = 0; i < 8; i++)
#pragma unroll
            for (int j = 0; j < 8; j++)
                acc[i][j] = fmaf(a_[i], b_[j], acc[i][j]);
    }

#pragma unroll
    for (int i = 0; i < 8; i++){
        int mm = m0 + ((i < 4) ? ty*4 + i : 64 + ty*4 + (i-4));
        float bsv = bias ? bias[mm] : 0.f;
        float* crow = C + (long)mm*Nn + n0;
        *(float4*)&crow[tx*4]      = make_float4(acc[i][0]+bsv,acc[i][1]+bsv,acc[i][2]+bsv,acc[i][3]+bsv);
        *(float4*)&crow[tx*4 + 64] = make_float4(acc[i][4]+bsv,acc[i][5]+bsv,acc[i][6]+bsv,acc[i][7]+bsv);
    }
}

// ---------------- small GEMMs (64x64 tile) for attention --------------------
__global__ void gemm_nn(const float* __restrict__ A, const float* __restrict__ Bm,
                        float* __restrict__ C, const float* __restrict__ bias,
                        int M, int Nn, int Kk, long sA, long sB, long sC)
{
    A  += (long)blockIdx.z * sA;
    Bm += (long)blockIdx.z * sB;
    C  += (long)blockIdx.z * sC;
    __shared__ float As[16][68];
    __shared__ float Bs[16][64];
    int tid = threadIdx.x;
    int m0 = blockIdx.y * 64, n0 = blockIdx.x * 64;
    int ty = tid >> 4, tx = tid & 15;
    float acc[4][4] = {};
    for (int k0 = 0; k0 < Kk; k0 += 16){
#pragma unroll
        for (int i = tid; i < 1024; i += 256){
            int rr = i >> 4, cc = i & 15;
            int mm = m0 + rr, kk = k0 + cc;
            As[cc][rr] = (mm < M && kk < Kk) ? A[(long)mm*Kk + kk] : 0.f;
        }
#pragma unroll
        for (int i = tid; i < 1024; i += 256){
            int rr = i >> 6, cc = i & 63;
            int kk = k0 + rr;
            Bs[rr][cc] = (kk < Kk) ? Bm[(long)kk*Nn + n0 + cc] : 0.f;
        }
        __syncthreads();
#pragma unroll
        for (int kk = 0; kk < 16; kk++){
            float4 a  = *(const float4*)&As[kk][ty*4];
            float4 bv = *(const float4*)&Bs[kk][tx*4];
            float av[4] = {a.x, a.y, a.z, a.w};
            float bb[4] = {bv.x, bv.y, bv.z, bv.w};
#pragma unroll
            for (int i = 0; i < 4; i++)
#pragma unroll
                for (int j = 0; j < 4; j++)
                    acc[i][j] = fmaf(av[i], bb[j], acc[i][j]);
        }
        __syncthreads();
    }
#pragma unroll
    for (int i = 0; i < 4; i++){
        int mm = m0 + ty*4 + i;
        if (mm < M){
            float bsv = bias ? bias[mm] : 0.f;
            float4 o = make_float4(acc[i][0]+bsv, acc[i][1]+bsv, acc[i][2]+bsv, acc[i][3]+bsv);
            *(float4*)&C[(long)mm*Nn + n0 + tx*4] = o;
        }
    }
}

__global__ void gemm_tn(const float* __restrict__ A, const float* __restrict__ Bm,
                        float* __restrict__ C,
                        int M, int Nn, int Kk, int lda, int ldb,
                        long sA, long sB, long sC)
{
    A += (long)blockIdx.z*sA; Bm += (long)blockIdx.z*sB; C += (long)blockIdx.z*sC;
    __shared__ float As[16][64], Bs[16][64];
    int tid = threadIdx.x;
    int m0 = blockIdx.y * 64, n0 = blockIdx.x * 64;
    int ty = tid >> 4, tx = tid & 15;
    float acc[4][4] = {};
    for (int k0 = 0; k0 < Kk; k0 += 16){
#pragma unroll
        for (int i = tid; i < 1024; i += 256){
            int rr = i >> 6, cc = i & 63;
            int kk = k0 + rr;
            As[rr][cc] = (kk < Kk) ? A[(long)kk*lda + m0 + cc] : 0.f;
            Bs[rr][cc] = (kk < Kk) ? Bm[(long)kk*ldb + n0 + cc] : 0.f;
        }
        __syncthreads();
#pragma unroll
        for (int kk = 0; kk < 16; kk++){
            float4 a  = *(const float4*)&As[kk][ty*4];
            float4 bv = *(const float4*)&Bs[kk][tx*4];
            float av[4] = {a.x, a.y, a.z, a.w};
            float bb[4] = {bv.x, bv.y, bv.z, bv.w};
#pragma unroll
            for (int i = 0; i < 4; i++)
#pragma unroll
                for (int j = 0; j < 4; j++)
                    acc[i][j] = fmaf(av[i], bb[j], acc[i][j]);
        }
        __syncthreads();
    }
#pragma unroll
    for (int i = 0; i < 4; i++){
        int mm = m0 + ty*4 + i;
        float4 o = make_float4(acc[i][0], acc[i][1], acc[i][2], acc[i][3]);
        *(float4*)&C[(long)mm*Nn + n0 + tx*4] = o;
    }
}

__global__ void gemm_nt(const float* __restrict__ A, const float* __restrict__ Bm,
                        float* __restrict__ C,
                        int M, int Nn, int Kk, int lda, int ldb,
                        long sA, long sB, long sC)
{
    A += (long)blockIdx.z*sA; Bm += (long)blockIdx.z*sB; C += (long)blockIdx.z*sC;
    __shared__ float As[16][68], Bs[16][68];
    int tid = threadIdx.x;
    int m0 = blockIdx.y * 64, n0 = blockIdx.x * 64;
    int ty = tid >> 4, tx = tid & 15;
    float acc[4][4] = {};
    for (int k0 = 0; k0 < Kk; k0 += 16){
#pragma unroll
        for (int i = tid; i < 1024; i += 256){
            int mm = i >> 4, kd = i & 15;
            int kk = k0 + kd;
            As[kd][mm] = (kk < Kk) ? A[(long)(m0+mm)*lda + kk] : 0.f;
            Bs[kd][mm] = (kk < Kk) ? Bm[(long)(n0+mm)*ldb + kk] : 0.f;
        }
        __syncthreads();
#pragma unroll
        for (int kk = 0; kk < 16; kk++){
            float4 a  = *(const float4*)&As[kk][ty*4];
            float4 bv = *(const float4*)&Bs[kk][tx*4];
            float av[4] = {a.x, a.y, a.z, a.w};
            float bb[4] = {bv.x, bv.y, bv.z, bv.w};
#pragma unroll
            for (int i = 0; i < 4; i++)
#pragma unroll
                for (int j = 0; j < 4; j++)
                    acc[i][j] = fmaf(av[i], bb[j], acc[i][j]);
        }
        __syncthreads();
    }
#pragma unroll
    for (int i = 0; i < 4; i++){
        int mm = m0 + ty*4 + i;
        float4 o = make_float4(acc[i][0], acc[i][1], acc[i][2], acc[i][3]);
        *(float4*)&C[(long)mm*Nn + n0 + tx*4] = o;
    }
}

// ---- Kahan-compensated fp32 GEMMs for the channel-attention path ----------
__global__ void gemm_nt_kah(const float* __restrict__ A, const float* __restrict__ Bm,
                            float* __restrict__ C,
                            int M, int Nn, int Kk, int lda, int ldb,
                            long sA, long sB, long sC)
{
    A += (long)blockIdx.z*sA; Bm += (long)blockIdx.z*sB; C += (long)blockIdx.z*sC;
    __shared__ float As[16][68], Bs[16][68];
    int tid = threadIdx.x;
    int m0 = blockIdx.y * 64, n0 = blockIdx.x * 64;
    int ty = tid >> 4, tx = tid & 15;
    float acc[4][4] = {};
    float cmp[4][4] = {};
    for (int k0 = 0; k0 < Kk; k0 += 16){
#pragma unroll
        for (int i = tid; i < 1024; i += 256){
            int mm = i >> 4, kd = i & 15;
            int kk = k0 + kd;
            As[kd][mm] = (kk < Kk) ? A[(long)(m0+mm)*lda + kk] : 0.f;
            Bs[kd][mm] = (kk < Kk) ? Bm[(long)(n0+mm)*ldb + kk] : 0.f;
        }
        __syncthreads();
#pragma unroll
        for (int kk = 0; kk < 16; kk++){
            float4 a  = *(const float4*)&As[kk][ty*4];
            float4 bv = *(const float4*)&Bs[kk][tx*4];
            float av[4] = {a.x, a.y, a.z, a.w};
            float bb[4] = {bv.x, bv.y, bv.z, bv.w};
#pragma unroll
            for (int i = 0; i < 4; i++)
#pragma unroll
                for (int j = 0; j < 4; j++){
                    float y = fmaf(av[i], bb[j], -cmp[i][j]);
                    float t = acc[i][j] + y;
                    cmp[i][j] = (t - acc[i][j]) - y;
                    acc[i][j] = t;
                }
        }
        __syncthreads();
    }
#pragma unroll
    for (int i = 0; i < 4; i++){
        int mm = m0 + ty*4 + i;
        float4 o = make_float4(acc[i][0], acc[i][1], acc[i][2], acc[i][3]);
        *(float4*)&C[(long)mm*Nn + n0 + tx*4] = o;
    }
}

__global__ void gemm_nn_kah(const float* __restrict__ A, const float* __restrict__ Bm,
                            float* __restrict__ C,
                            int M, int Nn, int Kk, long sA, long sB, long sC)
{
    A  += (long)blockIdx.z * sA;
    Bm += (long)blockIdx.z * sB;
    C  += (long)blockIdx.z * sC;
    __shared__ float As[16][68];
    __shared__ float Bs[16][64];
    int tid = threadIdx.x;
    int m0 = blockIdx.y * 64, n0 = blockIdx.x * 64;
    int ty = tid >> 4, tx = tid & 15;
    float acc[4][4] = {};
    float cmp[4][4] = {};
    for (int k0 = 0; k0 < Kk; k0 += 16){
#pragma unroll
        for (int i = tid; i < 1024; i += 256){
            int rr = i >> 4, cc = i & 15;
            int mm = m0 + rr, kk = k0 + cc;
            As[cc][rr] = (mm < M && kk < Kk) ? A[(long)mm*Kk + kk] : 0.f;
        }
#pragma unroll
        for (int i = tid; i < 1024; i += 256){
            int rr = i >> 6, cc = i & 63;
            int kk = k0 + rr;
            Bs[rr][cc] = (kk < Kk) ? Bm[(long)kk*Nn + n0 + cc] : 0.f;
        }
        __syncthreads();
#pragma unroll
        for (int kk = 0; kk < 16; kk++){
            float4 a  = *(const float4*)&As[kk][ty*4];
            float4 bv = *(const float4*)&Bs[kk][tx*4];
            float av[4] = {a.x, a.y, a.z, a.w};
            float bb[4] = {bv.x, bv.y, bv.z, bv.w};
#pragma unroll
            for (int i = 0; i < 4; i++)
#pragma unroll
                for (int j = 0; j < 4; j++){
                    float y = fmaf(av[i], bb[j], -cmp[i][j]);
                    float t = acc[i][j] + y;
                    cmp[i][j] = (t - acc[i][j]) - y;
                    acc[i][j] = t;
                }
        }
        __syncthreads();
    }
#pragma unroll
    for (int i = 0; i < 4; i++){
        int mm = m0 + ty*4 + i;
        float4 o = make_float4(acc[i][0], acc[i][1], acc[i][2], acc[i][3]);
        *(float4*)&C[(long)mm*Nn + n0 + tx*4] = o;
    }
}

// ---------------- BatchNorm stats (f32 bulk, f64 finalize) -------------------
__global__ void bn_stats_part(const float* __restrict__ Xs)
{
    int c = blockIdx.x, blk = blockIdx.y;
    const float4* xp = (const float4*)(Xs + (size_t)c * P_ + (size_t)blk * (P_/8));
    int tid = threadIdx.x;
    float s = 0.f, ss = 0.f;
    const int nvec = (P_/8)/4;      // 4096 float4 -> 16/thread
    for (int p = tid; p < nvec; p += 256){
        float4 v = xp[p];
        s  += v.x + v.y + v.z + v.w;
        ss = fmaf(v.x, v.x, ss); ss = fmaf(v.y, v.y, ss);
        ss = fmaf(v.z, v.z, ss); ss = fmaf(v.w, v.w, ss);
    }
    __shared__ float sh0[256], sh1[256];
    sh0[tid] = s; sh1[tid] = ss; __syncthreads();
    for (int off = 128; off; off >>= 1){
        if (tid < off){ sh0[tid] += sh0[tid+off]; sh1[tid] += sh1[tid+off]; }
        __syncthreads();
    }
    if (tid == 0){
        g_part[(c*8 + blk)*2 + 0] = (double)sh0[0];
        g_part[(c*8 + blk)*2 + 1] = (double)sh1[0];
    }
}

// finalize: mean/istd + publish per-channel BN params into g_prm[coff..)
__global__ void bn_stats_final(int C, int coff, const float* __restrict__ gg,
                               const float* __restrict__ be)
{
    int c = threadIdx.x;
    if (c < C){
        double s = 0.0, ss = 0.0;
#pragma unroll
        for (int j = 0; j < 8; j++){
            s  += g_part[(c*8+j)*2+0];
            ss += g_part[(c*8+j)*2+1];
        }
        double m   = s / (double)P_;
        double var = ss / (double)P_ - m*m;
        float mf = (float)m;
        float isf = (float)(1.0 / sqrt(var + 1e-5));
        g_mean[c] = mf;
        g_istd[c] = isf;
        if (coff >= 0)
            g_prm[coff + c] = make_float4(mf, isf * gg[c], be[c], 0.f);
    }
}

// ------- fused layer-4 BN + ReLU + max over K --------------------------------
__global__ void bn_relu_maxk(const float* __restrict__ Xs,
                             const float* __restrict__ gg, const float* __restrict__ be)
{
    int i = blockIdx.x * 256 + threadIdx.x;           // over B*COUT*S = 2^20
    int s = i & 1023, c = (i >> 10) & 255, b = i >> 18;
    float m = g_mean[c], is = g_istd[c], gv = gg[c], bb = be[c];
    float sc = is * gv;
    const float4* src = (const float4*)(Xs + (size_t)c * P_ + ((size_t)(b*S_ + s)) * K_);
    float best = 0.f;
#pragma unroll
    for (int k = 0; k < 8; k++){
        float4 v = src[k];
        best = fmaxf(best, (v.x - m)*sc + bb);
        best = fmaxf(best, (v.y - m)*sc + bb);
        best = fmaxf(best, (v.z - m)*sc + bb);
        best = fmaxf(best, (v.w - m)*sc + bb);
    }
    g_feat[i] = best;
}

// ---------------- softmaxes ---------------------------------------------------
__global__ void softmax_rows_1024(float* __restrict__ E)
{
    int row = blockIdx.x;
    float* e = E + (size_t)row * 1024;
    int tid = threadIdx.x;
    __shared__ float sh[256];
    float mx = -3.402823466e38f;
    for (int c = tid; c < 1024; c += 256) mx = fmaxf(mx, e[c]);
    sh[tid] = mx; __syncthreads();
    for (int off = 128; off; off >>= 1){ if (tid < off) sh[tid] = fmaxf(sh[tid], sh[tid+off]); __syncthreads(); }
    mx = sh[0]; __syncthreads();
    float sum = 0.f;
    float vals[4];
#pragma unroll
    for (int q = 0; q < 4; q++){
        int c = tid + q*256;
        float v = expf(e[c] - mx);
        vals[q] = v; sum += v;
    }
    sh[tid] = sum; __syncthreads();
    for (int off = 128; off; off >>= 1){ if (tid < off) sh[tid] += sh[tid+off]; __syncthreads(); }
    float inv = 1.0f / sh[0];
#pragma unroll
    for (int q = 0; q < 4; q++) e[tid + q*256] = vals[q] * inv;
}

__global__ void softmax_c_kernel(float* __restrict__ E)
{
    int row = blockIdx.x;                   // B*COUT rows of 256
    float* e = E + (size_t)row * 256;
    int tid = threadIdx.x;
    __shared__ double sh[256];
    double v = (double)e[tid];
    sh[tid] = v; __syncthreads();
    for (int off = 128; off; off >>= 1){ if (tid < off) sh[tid] = fmax(sh[tid], sh[tid+off]); __syncthreads(); }
    double m1 = sh[0]; __syncthreads();
    double t = m1 - v;
    sh[tid] = t; __syncthreads();
    for (int off = 128; off; off >>= 1){ if (tid < off) sh[tid] = fmax(sh[tid], sh[tid+off]); __syncthreads(); }
    double mt = sh[0]; __syncthreads();
    double ex = exp(t - mt);
    sh[tid] = ex; __syncthreads();
    for (int off = 128; off; off >>= 1){ if (tid < off) sh[tid] += sh[tid+off]; __syncthreads(); }
    e[tid] = (float)(ex / sh[0]);
}

// ---------------- finalize -----------------------------------------------------
__global__ void finalize_kernel(float* __restrict__ out, const float* __restrict__ gamma)
{
    int i = blockIdx.x * 256 + threadIdx.x;   // output-major (b,s,c), 2^20 total
    int c = i & 255, s = (i >> 8) & 1023, b = i >> 18;
    size_t f = ((size_t)(b*COUT_ + c)) * S_ + s;
    float g = gamma[0];
    float val = g * (g_outp[f] + g_outc[f]) + 2.0f * g_feat[f];
    out[(size_t)B_*S_*3 + i] = val;
}

// ---------------- launch -------------------------------------------------------
extern "C" void kernel_launch(void* const* d_in, const int* in_sizes, int n_in,
                              void* d_out, int out_size)
{
    const float* xyz    = (const float*)d_in[0];
    const float* points = (const float*)d_in[1];
    const float* W[4]  = {(const float*)d_in[2],  (const float*)d_in[6],
                          (const float*)d_in[10], (const float*)d_in[14]};
    const float* gl[4] = {(const float*)d_in[4],  (const float*)d_in[8],
                          (const float*)d_in[12], (const float*)d_in[16]};
    const float* bel[4]= {(const float*)d_in[5],  (const float*)d_in[9],
                          (const float*)d_in[13], (const float*)d_in[17]};
    const float* Wq = (const float*)d_in[18]; const float* bq = (const float*)d_in[19];
    const float* Wk = (const float*)d_in[20]; const float* bk = (const float*)d_in[21];
    const float* Wv = (const float*)d_in[22]; const float* bv = (const float*)d_in[23];
    const float* gamma = (const float*)d_in[24];
    float* out = (float*)d_out;

    float *Y, *Xs, *Wt, *feat, *q, *k, *v, *E, *Ec, *outp, *outc;
    float4* prm;
    cudaGetSymbolAddress((void**)&Y,    g_Y);
    cudaGetSymbolAddress((void**)&Xs,   g_Xs);
    cudaGetSymbolAddress((void**)&Wt,   g_Wt);
    cudaGetSymbolAddress((void**)&prm,  g_prm);
    cudaGetSymbolAddress((void**)&feat, g_feat);
    cudaGetSymbolAddress((void**)&q,    g_q);
    cudaGetSymbolAddress((void**)&k,    g_k);
    cudaGetSymbolAddress((void**)&v,    g_v);
    cudaGetSymbolAddress((void**)&E,    g_E);
    cudaGetSymbolAddress((void**)&Ec,   g_Ec);
    cudaGetSymbolAddress((void**)&outp, g_outp);
    cudaGetSymbolAddress((void**)&outc, g_outc);

    int   Kl[4]  = {CIN_, CIN_+HID_, CIN_+2*HID_, CIN_+3*HID_};
    int   COl[4] = {HID_, HID_, HID_, COUT_};
    long Woff[4];
    {
        long o = 0;
        for (int l = 0; l < 4; l++){ Woff[l] = o; o += (long)Kl[l]*COl[l]; }
    }

    // hoisted: BN-param identity init + weight transposes
    init_prm<<<3, 256>>>();
    for (int l = 0; l < 4; l++){
        int Melem = COl[l]*Kl[l];
        transposeW<<<(Melem + 255)/256, 256>>>(W[l], Wt + Woff[l], COl[l], Kl[l]);
    }

    // stage 1-2: FPS, ball query, gather/build x0
    fps_kernel<<<B_, 1024>>>(xyz, out);
    ball_kernel<<<(B_*S_*32)/256, 256>>>(xyz);
    build_x0<<<B_*S_, 256>>>(xyz, points);

    // stage 3: DenseNet — conv writes RAW into Y-slot (or Xs for L4);
    // BN folded into subsequent GEMM B-loads via g_prm.
    float* rawdst[4] = {Y + (size_t)CIN_*P_, Y + (size_t)(CIN_+HID_)*P_,
                        Y + (size_t)(CIN_+2*HID_)*P_, Xs};
    for (int l = 0; l < 4; l++){
        gemm128db<<<dim3(P_/128, COl[l]/128, 1), 256>>>(Wt + Woff[l], Y, rawdst[l],
                                                        nullptr, prm,
                                                        COl[l], P_, Kl[l], 0, 0);
        bn_stats_part<<<dim3(COl[l], 8), 256>>>(rawdst[l]);
        bn_stats_final<<<1, 256>>>(COl[l], (l < 3) ? Kl[l] : -1, gl[l], bel[l]);
        if (l == 3)
            bn_relu_maxk<<<(B_*COUT_*S_)/256, 256>>>(Xs, gl[l], bel[l]);
    }

    // stage 5: dual attention (all 64-tile kernels — R5 config)
    long fS = (long)COUT_ * S_;
    gemm_nn<<<dim3(S_/64, 1, B_), 256>>>(Wq, feat, q, bq, C8_,  S_, COUT_, 0, fS, (long)C8_*S_);
    gemm_nn<<<dim3(S_/64, 1, B_), 256>>>(Wk, feat, k, bk, C8_,  S_, COUT_, 0, fS, (long)C8_*S_);
    gemm_nn<<<dim3(S_/64, 4, B_), 256>>>(Wv, feat, v, bv, COUT_,S_, COUT_, 0, fS, fS);

    gemm_tn<<<dim3(S_/64, S_/64, B_), 256>>>(q, k, E, S_, S_, C8_, S_, S_,
                                             (long)C8_*S_, (long)C8_*S_, (long)S_*S_);
    softmax_rows_1024<<<B_*S_, 256>>>(E);
    gemm_nt<<<dim3(S_/64, COUT_/64, B_), 256>>>(v, E, outp, COUT_, S_, S_, S_, S_,
                                                fS, (long)S_*S_, fS);

    // channel attention — Kahan-compensated fp32 energy + out_c, f64 softmax
    gemm_nt_kah<<<dim3(COUT_/64, COUT_/64, B_), 256>>>(
        feat, feat, Ec, COUT_, COUT_, S_, S_, S_, fS, fS, (long)COUT_*COUT_);
    softmax_c_kernel<<<B_*COUT_, 256>>>(Ec);
    gemm_nn_kah<<<dim3(S_/64, COUT_/64, B_), 256>>>(
        Ec, feat, outc, COUT_, S_, COUT_, (long)COUT_*COUT_, fS, fS);

    finalize_kernel<<<(B_*S_*COUT_)/256, 256>>>(out, gamma);
}